// round 16
// baseline (speedup 1.0000x reference)
#include <cuda_runtime.h>
#include <cstdint>

#define DD 8
#define BB 8
#define NN 2048
#define NN2 (NN * NN)        // 4194304

// 64-bit spike mask per presynaptic neuron e: bit (d*8+b) set iff Xd[d,b,e]==1
__device__ unsigned long long g_spike[NN];

__device__ __forceinline__ unsigned smem_u32(const void* p) {
    return (unsigned)__cvta_generic_to_shared(p);
}

// ---------------------------------------------------------------------------
// Kernel 1: ballot-pack spike masks (one warp per e) + zero output.
// ---------------------------------------------------------------------------
__global__ void __launch_bounds__(256)
pack_kernel(const float* __restrict__ Xd, float* __restrict__ out) {
    const int gid  = blockIdx.x * 256 + threadIdx.x;
    const int lane = threadIdx.x & 31;
    const int e    = gid >> 5;                       // global warp id = e

    const bool s0 = Xd[(size_t)lane        * NN + e] > 0.5f;
    const bool s1 = Xd[(size_t)(lane + 32) * NN + e] > 0.5f;
    const unsigned lo = __ballot_sync(0xFFFFFFFFu, s0);
    const unsigned hi = __ballot_sync(0xFFFFFFFFu, s1);
    if (lane == 0)
        g_spike[e] = (unsigned long long)lo | ((unsigned long long)hi << 32);

    if (gid < BB * NN) out[gid] = 0.0f;
}

// ---------------------------------------------------------------------------
// Kernel 2: fused gate + blend + reduce over 16e x 128o tiles.
//   Stream overlap engineered so ALL THREE DRAM streams start immediately:
//     0. Per-warp active-row mask from g_spike (fold+ballot) -> L2 prefetch
//        of this batch's active Wlong rows (predicate independent of dm!)
//     1. cp.async statics (S,W,F) global->smem
//     2. Phase A1: spike-gated delaymap read (~2.7/8 planes) -> gate words
//     3. cp.async wait + barrier
//     4. Phase B (warp = batch b, lane = o-quad): ffs loop over active rows;
//        Wlong LDG.128 now L2-hot. 32-bit offsets throughout.
// ---------------------------------------------------------------------------
#define ET 16
#define OT 128

__global__ void __launch_bounds__(256)
fused_kernel(const float4* __restrict__ dm4,   // delaymap (D,N,N)
             const float4* __restrict__ W4,    // (N,N)
             const float*  __restrict__ Wl,    // Wlong (B,N,N)
             const float4* __restrict__ F4,    // STDP_frac (N,N)
             const float4* __restrict__ S4,    // signs (N,N)
             float* __restrict__ out)          // (B,N)
{
    __shared__ float    sS[ET][OT];        // 8 KB
    __shared__ float    sW[ET][OT];        // 8 KB
    __shared__ float    sF[ET][OT];        // 8 KB
    __shared__ unsigned sG[ET][OT / 4];    // 2 KB packed gate words

    const int t     = threadIdx.x;
    const int lane  = t & 31;
    const int w     = t >> 5;
    const int obase = blockIdx.x * OT;
    const int ebase = blockIdx.y * ET;
    const int b     = w;                              // Phase-B batch of this warp

    // ---- Step 0: active-row mask for batch b + Wlong L2 prefetch ----
    // lane ee < ET reads g_spike[ebase+ee]; row active iff batch b spiked
    // at any delay. Ballot -> 16-bit mask, warp-uniform thereafter.
    unsigned rowmask;
    {
        bool act = false;
        if (lane < ET) {
            unsigned long long bits = g_spike[ebase + lane];
            unsigned long long u = bits | (bits >> 32);
            u |= u >> 16;
            u |= u >> 8;
            act = (u >> b) & 1ull;
        }
        rowmask = __ballot_sync(0xFFFFFFFFu, act);    // bits 0..15
    }
    const float4* __restrict__ wlb = (const float4*)(Wl + (size_t)b * NN2);
    const unsigned wbase = (unsigned)(ebase * (NN / 4) + obase / 4 + lane);
    {
        unsigned m = rowmask;
        while (m) {                                   // ~5.4 iters, warp-uniform
            const int ee = __ffs(m) - 1;
            m &= m - 1;
            asm volatile("prefetch.global.L2 [%0];"
                         :: "l"(wlb + wbase + ee * (NN / 4)));
        }
    }

    // ---- Step 1: cp.async raw statics (2 float4 per thread per array) ----
#pragma unroll
    for (int k = 0; k < 2; k++) {
        const int idx = t + k * 256;                  // float4 index in tile
        const int ee  = idx >> 5;                     // 32 quads per row
        const int qq  = idx & 31;
        const unsigned g4 = (unsigned)((ebase + ee) * (NN / 4) + obase / 4 + qq);
        asm volatile("cp.async.cg.shared.global [%0], [%1], 16;\n"
                     :: "r"(smem_u32(&sS[ee][qq * 4])), "l"(S4 + g4));
        asm volatile("cp.async.cg.shared.global [%0], [%1], 16;\n"
                     :: "r"(smem_u32(&sW[ee][qq * 4])), "l"(W4 + g4));
        asm volatile("cp.async.cg.shared.global [%0], [%1], 16;\n"
                     :: "r"(smem_u32(&sF[ee][qq * 4])), "l"(F4 + g4));
    }
    asm volatile("cp.async.commit_group;\n");

    // ---- Step 2 (Phase A1): gates; warp -> rows 2w, 2w+1 ----
#pragma unroll
    for (int r = 0; r < 2; r++) {
        const int el = w * 2 + r;
        const int e  = ebase + el;
        const unsigned long long bits = g_spike[e];   // uniform (L2-resident)
        unsigned g0 = 0, g1 = 0, g2 = 0, g3 = 0;
#pragma unroll
        for (int d = 0; d < DD; d++) {
            const unsigned m8 = (unsigned)(bits >> (d * 8)) & 0xFFu;
            if (m8) {                                 // warp-uniform branch
                const float4 v =
                    dm4[(size_t)d * (NN2 / 4) + (unsigned)(e * (NN / 4) + obase / 4 + lane)];
                if (v.x > 0.5f) g0 = m8;              // one-hot: <=1 match
                if (v.y > 0.5f) g1 = m8;
                if (v.z > 0.5f) g2 = m8;
                if (v.w > 0.5f) g3 = m8;
            }
        }
        sG[el][lane] = g0 | (g1 << 8) | (g2 << 16) | (g3 << 24);
    }

    // ---- Step 3: wait for statics + make smem visible ----
    asm volatile("cp.async.wait_group 0;\n");
    __syncthreads();

    // ---- Step 4 (Phase B): ffs loop over active rows; Wlong is L2-hot ----
    float a0 = 0.f, a1 = 0.f, a2 = 0.f, a3 = 0.f;
    unsigned m = rowmask;
    while (m) {                                       // warp-uniform, ~5.4 iters
        const int ee = __ffs(m) - 1;
        m &= m - 1;

        const unsigned gs = sG[ee][lane] >> b;        // bits 0/8/16/24 = gates
        const float4 wl = wlb[wbase + ee * (NN / 4)]; // L2 hit (prefetched)
        const float4 sv = *(const float4*)&sS[ee][lane * 4];
        const float4 wv = *(const float4*)&sW[ee][lane * 4];
        const float4 fv = *(const float4*)&sF[ee][lane * 4];
        // s * (w*(1-f) + f*wl) = s * fma(f, wl - w, w)
        a0 += (gs & 0x00000001u) ? sv.x * fmaf(fv.x, wl.x - wv.x, wv.x) : 0.0f;
        a1 += (gs & 0x00000100u) ? sv.y * fmaf(fv.y, wl.y - wv.y, wv.y) : 0.0f;
        a2 += (gs & 0x00010000u) ? sv.z * fmaf(fv.z, wl.z - wv.z, wv.z) : 0.0f;
        a3 += (gs & 0x01000000u) ? sv.w * fmaf(fv.w, wl.w - wv.w, wv.w) : 0.0f;
    }

    float* op = out + b * NN + obase + lane * 4;
    atomicAdd(op + 0, a0);
    atomicAdd(op + 1, a1);
    atomicAdd(op + 2, a2);
    atomicAdd(op + 3, a3);
}

// ---------------------------------------------------------------------------
// Launch
// ---------------------------------------------------------------------------
extern "C" void kernel_launch(void* const* d_in, const int* in_sizes, int n_in,
                              void* d_out, int out_size) {
    const float* Xd = (const float*)d_in[0];   // (D,B,N)
    const float* dm = (const float*)d_in[1];   // (D,N,N)
    const float* W  = (const float*)d_in[2];   // (N,N)
    const float* Wl = (const float*)d_in[3];   // (B,N,N)
    const float* F  = (const float*)d_in[4];   // (N,N)
    const float* S  = (const float*)d_in[5];   // (N,N)
    float* out = (float*)d_out;                // (B,N)

    pack_kernel<<<(NN * 32) / 256, 256>>>(Xd, out);   // 256 CTAs

    dim3 grid(NN / OT, NN / ET);                      // 16 x 128 = 2048 CTAs
    fused_kernel<<<grid, 256>>>((const float4*)dm, (const float4*)W, Wl,
                                (const float4*)F, (const float4*)S, out);
}

// round 17
// speedup vs baseline: 1.0492x; 1.0492x over previous
#include <cuda_runtime.h>
#include <cstdint>

#define DD 8
#define BB 8
#define NN 2048
#define NN2 (NN * NN)        // 4194304

// 64-bit spike mask per presynaptic neuron e: bit (d*8+b) set iff Xd[d,b,e]==1
__device__ unsigned long long g_spike[NN];

__device__ __forceinline__ unsigned smem_u32(const void* p) {
    return (unsigned)__cvta_generic_to_shared(p);
}

// ---------------------------------------------------------------------------
// Kernel 1: ballot-pack spike masks (one warp per e) + zero output.
// ---------------------------------------------------------------------------
__global__ void __launch_bounds__(256)
pack_kernel(const float* __restrict__ Xd, float* __restrict__ out) {
    const int gid  = blockIdx.x * 256 + threadIdx.x;
    const int lane = threadIdx.x & 31;
    const int e    = gid >> 5;                       // global warp id = e

    const bool s0 = Xd[(size_t)lane        * NN + e] > 0.5f;
    const bool s1 = Xd[(size_t)(lane + 32) * NN + e] > 0.5f;
    const unsigned lo = __ballot_sync(0xFFFFFFFFu, s0);
    const unsigned hi = __ballot_sync(0xFFFFFFFFu, s1);
    if (lane == 0)
        g_spike[e] = (unsigned long long)lo | ((unsigned long long)hi << 32);

    if (gid < BB * NN) out[gid] = 0.0f;
}

// ---------------------------------------------------------------------------
// Kernel 2: fused gate + blend + reduce over 16e x 128o tiles (R15 skeleton).
//     1. cp.async statics (S,W,F) global->smem: issued FIRST
//     2. Phase A1: spike-gated delaymap read (~2.7/8 planes) -> gate words
//     3. cp.async wait + barrier
//     4. Phase B: warp = batch b, lane = o-quad. Active-row mask via one
//        ballot from sU; ffs loop SOFTWARE-PIPELINED: row k+1's Wlong LDG
//        issues before row k's FMAs consume, hiding DRAM latency across
//        the ~5.4 active iterations.
// ---------------------------------------------------------------------------
#define ET 16
#define OT 128

__global__ void __launch_bounds__(256)
fused_kernel(const float4* __restrict__ dm4,   // delaymap (D,N,N)
             const float4* __restrict__ W4,    // (N,N)
             const float*  __restrict__ Wl,    // Wlong (B,N,N)
             const float4* __restrict__ F4,    // STDP_frac (N,N)
             const float4* __restrict__ S4,    // signs (N,N)
             float* __restrict__ out)          // (B,N)
{
    __shared__ float    sS[ET][OT];        // 8 KB
    __shared__ float    sW[ET][OT];        // 8 KB
    __shared__ float    sF[ET][OT];        // 8 KB
    __shared__ unsigned sG[ET][OT / 4];    // 2 KB packed gate words
    __shared__ unsigned sU[ET];            // per-row batch-union byte

    const int t     = threadIdx.x;
    const int lane  = t & 31;
    const int w     = t >> 5;
    const int obase = blockIdx.x * OT;
    const int ebase = blockIdx.y * ET;

    // ---- Step 1: cp.async raw statics (2 float4 per thread per array) ----
#pragma unroll
    for (int k = 0; k < 2; k++) {
        const int idx = t + k * 256;                  // float4 index in tile
        const int ee  = idx >> 5;                     // 32 quads per row
        const int qq  = idx & 31;
        const size_t g4 = ((size_t)(ebase + ee) * NN + obase) / 4 + qq;
        asm volatile("cp.async.cg.shared.global [%0], [%1], 16;\n"
                     :: "r"(smem_u32(&sS[ee][qq * 4])), "l"(S4 + g4));
        asm volatile("cp.async.cg.shared.global [%0], [%1], 16;\n"
                     :: "r"(smem_u32(&sW[ee][qq * 4])), "l"(W4 + g4));
        asm volatile("cp.async.cg.shared.global [%0], [%1], 16;\n"
                     :: "r"(smem_u32(&sF[ee][qq * 4])), "l"(F4 + g4));
    }
    asm volatile("cp.async.commit_group;\n");

    // ---- Step 2 (Phase A1): gates; warp -> rows 2w, 2w+1 ----
#pragma unroll
    for (int r = 0; r < 2; r++) {
        const int el = w * 2 + r;
        const int e  = ebase + el;
        const unsigned long long bits = g_spike[e];   // uniform (L2-resident)
        unsigned g0 = 0, g1 = 0, g2 = 0, g3 = 0;
#pragma unroll
        for (int d = 0; d < DD; d++) {
            const unsigned m8 = (unsigned)(bits >> (d * 8)) & 0xFFu;
            if (m8) {                                 // warp-uniform branch
                const float4 v =
                    dm4[((size_t)d * NN + e) * (NN / 4) + obase / 4 + lane];
                if (v.x > 0.5f) g0 = m8;              // one-hot: <=1 match
                if (v.y > 0.5f) g1 = m8;
                if (v.z > 0.5f) g2 = m8;
                if (v.w > 0.5f) g3 = m8;
            }
        }
        sG[el][lane] = g0 | (g1 << 8) | (g2 << 16) | (g3 << 24);
        if (lane == 0) {
            unsigned long long u = bits | (bits >> 32);
            u |= u >> 16;
            u |= u >> 8;
            sU[el] = (unsigned)u & 0xFFu;             // bit b: batch b spiked
        }
    }

    // ---- Step 3: wait for statics + make smem visible ----
    asm volatile("cp.async.wait_group 0;\n");
    __syncthreads();

    // ---- Step 4 (Phase B): pipelined ffs loop over active rows ----
    const int b = w;
    const float4* __restrict__ wlb = (const float4*)(Wl + (size_t)b * NN2)
                                   + ((size_t)ebase * NN + obase) / 4 + lane;

    // Active-row mask: one broadcast LDS + ballot (warp-uniform result)
    const bool act = (lane < ET) && ((sU[lane] >> b) & 1u);
    unsigned m = __ballot_sync(0xFFFFFFFFu, act);     // bits 0..15

    float a0 = 0.f, a1 = 0.f, a2 = 0.f, a3 = 0.f;

    int ee_cur = -1;
    float4 wl_cur = make_float4(0.f, 0.f, 0.f, 0.f);
    if (m) {
        ee_cur = __ffs(m) - 1;
        m &= m - 1;
        wl_cur = wlb[ee_cur * (NN / 4)];
    }
    while (ee_cur >= 0) {                             // warp-uniform, ~5.4 iters
        // Issue NEXT row's Wlong load before consuming current (pipelining)
        int ee_next = -1;
        float4 wl_next = make_float4(0.f, 0.f, 0.f, 0.f);
        if (m) {
            ee_next = __ffs(m) - 1;
            m &= m - 1;
            wl_next = wlb[ee_next * (NN / 4)];
        }

        const unsigned gs = sG[ee_cur][lane] >> b;    // bits 0/8/16/24 = gates
        const float4 sv = *(const float4*)&sS[ee_cur][lane * 4];
        const float4 wv = *(const float4*)&sW[ee_cur][lane * 4];
        const float4 fv = *(const float4*)&sF[ee_cur][lane * 4];
        // s * (w*(1-f) + f*wl) = s * fma(f, wl - w, w)
        a0 += (gs & 0x00000001u) ? sv.x * fmaf(fv.x, wl_cur.x - wv.x, wv.x) : 0.0f;
        a1 += (gs & 0x00000100u) ? sv.y * fmaf(fv.y, wl_cur.y - wv.y, wv.y) : 0.0f;
        a2 += (gs & 0x00010000u) ? sv.z * fmaf(fv.z, wl_cur.z - wv.z, wv.z) : 0.0f;
        a3 += (gs & 0x01000000u) ? sv.w * fmaf(fv.w, wl_cur.w - wv.w, wv.w) : 0.0f;

        ee_cur = ee_next;
        wl_cur = wl_next;
    }

    float* op = out + b * NN + obase + lane * 4;
    atomicAdd(op + 0, a0);
    atomicAdd(op + 1, a1);
    atomicAdd(op + 2, a2);
    atomicAdd(op + 3, a3);
}

// ---------------------------------------------------------------------------
// Launch
// ---------------------------------------------------------------------------
extern "C" void kernel_launch(void* const* d_in, const int* in_sizes, int n_in,
                              void* d_out, int out_size) {
    const float* Xd = (const float*)d_in[0];   // (D,B,N)
    const float* dm = (const float*)d_in[1];   // (D,N,N)
    const float* W  = (const float*)d_in[2];   // (N,N)
    const float* Wl = (const float*)d_in[3];   // (B,N,N)
    const float* F  = (const float*)d_in[4];   // (N,N)
    const float* S  = (const float*)d_in[5];   // (N,N)
    float* out = (float*)d_out;                // (B,N)

    pack_kernel<<<(NN * 32) / 256, 256>>>(Xd, out);   // 256 CTAs

    dim3 grid(NN / OT, NN / ET);                      // 16 x 128 = 2048 CTAs
    fused_kernel<<<grid, 256>>>((const float4*)dm, (const float4*)W, Wl,
                                (const float4*)F, (const float4*)S, out);
}